// round 14
// baseline (speedup 1.0000x reference)
#include <cuda_runtime.h>
#include <cstdint>

// ===========================================================================
// Problem: B=2, N=1024, E=512, H=8, d=64, KVC=1536, 3N=3072
// All MMA operands pre-rounded to tf32 (rna) in memory; GEMMs use a 2-stage
// cp.async pipeline with no in-loop conversion. Spatial attention flash-fused
// (split-KV, 3 streams batched); instance-norm variance via Gram identities:
//   sum(QK^T) = (sum q)·(sum k),  sum((QK^T)^2) = <Q^T Q, K^T K>.
// ===========================================================================

// ------------------------- scratch (__device__ globals) -------------------
__device__ float g_QCt [2*1536*1024];
__device__ float g_KCt [2*1536*1024];
__device__ float g_VC  [2*1024*1536];
__device__ float g_ATTC[2*1536*1536];
__device__ float g_CTXC[2*1536*1024];
__device__ float g_KVS [2*3072*512];
__device__ float g_KM  [2*3072*512];
__device__ float g_VMt [2*512*3072];
__device__ float g_KMt [2*512*3072 + 128*3072];
__device__ float g_QB3 [3*2*1024*512];
__device__ float g_QBt3[3*2*512*1024 + 64*1024];
__device__ float g_GQ  [48*128*64];
__device__ float g_GK  [16*128*64];
__device__ float g_PO  [2*48*1024*64];
__device__ float g_ML  [2*48*1024*2];
__device__ float g_CTXB3[3*2*1024*512];
__device__ float g_PART[16*256*2];
__device__ float g_SCALE[48];
// rounded copies of external inputs
__device__ float g_embCr[2*1024*1536];
__device__ float g_embr [3*2*1024*512];
__device__ float g_WqCr [1536*1536];
__device__ float g_WkCr [1536*1536];
__device__ float g_WvCr [1536*1536];
__device__ float g_Wkr  [512*512];
__device__ float g_Wvr  [512*512];
__device__ float g_Wqr  [3*512*512];
__device__ float g_Wor  [3*512*512];

// ------------------------- helpers ----------------------------------------
__device__ __forceinline__ uint32_t tf32rn(float x) {
    uint32_t r;
    asm("cvt.rna.tf32.f32 %0, %1;" : "=r"(r) : "f"(x));
    return r;
}
__device__ __forceinline__ float tf32rnf(float x) { return __uint_as_float(tf32rn(x)); }
__device__ __forceinline__ uint32_t smem_u32(const void* p) {
    uint32_t a;
    asm("{ .reg .u64 t; cvta.to.shared.u64 t, %1; cvt.u32.u64 %0, t; }" : "=r"(a) : "l"(p));
    return a;
}
__device__ __forceinline__ void cpasync16(uint32_t saddr, const void* g) {
    asm volatile("cp.async.cg.shared.global [%0], [%1], 16;" :: "r"(saddr), "l"(g) : "memory");
}
__device__ __forceinline__ void mma1688(float* c, const uint32_t* a, const uint32_t* b) {
    asm volatile(
        "mma.sync.aligned.m16n8k8.row.col.f32.tf32.tf32.f32 "
        "{%0,%1,%2,%3}, {%4,%5,%6,%7}, {%8,%9}, {%0,%1,%2,%3};"
        : "+f"(c[0]), "+f"(c[1]), "+f"(c[2]), "+f"(c[3])
        : "r"(a[0]), "r"(a[1]), "r"(a[2]), "r"(a[3]), "r"(b[0]), "r"(b[1]));
}

// ---------------------------------------------------------------------------
// round_many: batched elementwise tf32 rounding of external inputs
// ---------------------------------------------------------------------------
struct RoundJobs {
    const float4* src[15];
    float4*       dst[15];
    int           n4[15];
};
__global__ __launch_bounds__(256)
void round_many(RoundJobs j)
{
    const int b = blockIdx.y;
    const int n4 = j.n4[b];
    const float4* s = j.src[b];
    float4* d = j.dst[b];
    for (int i = blockIdx.x*256 + threadIdx.x; i < n4; i += gridDim.x*256) {
        float4 v = s[i];
        v.x = tf32rnf(v.x); v.y = tf32rnf(v.y);
        v.z = tf32rnf(v.z); v.w = tf32rnf(v.w);
        d[i] = v;
    }
}

// ===========================================================================
// cp.async tensor-core GEMM:  C[m,n] = sum_k A[m*lda+k] * B[n*ldb+k]
//   Operands MUST be tf32-exact in memory. BM=128, BK=32, BN in {64,128}.
//   2-stage double buffer. K/BK >= 2. z-batch as before.
// ===========================================================================
template<int BN, bool STATS, bool RND>
__global__ __launch_bounds__(256)
void mma_gemm(const float* __restrict__ A, const float* __restrict__ B, float* __restrict__ C,
              int K, int lda, int ldb, int ldc,
              long sAo, long sAi, long sBo, long sBi, long sCo, long sCi,
              int innerB, float* __restrict__ part)
{
    constexpr int BM  = 128, BK = 32, PAD = 36;
    constexpr int ASZ = BM * PAD;            // uint32 words
    constexpr int BSZ = BN * PAD;
    constexpr int WGN = (BN == 128) ? 4 : 2;
    constexpr int WM  = (BN == 128) ? 64 : 32;
    constexpr int WN  = 32;
    constexpr int MT  = WM / 16;
    constexpr int NT  = WN / 8;

    extern __shared__ uint32_t sm[];         // 2 stages x (ASZ + BSZ)

    const int z  = blockIdx.z;
    const int zo = z / innerB, zi = z % innerB;
    A += (long)zo * sAo + (long)zi * sAi;
    B += (long)zo * sBo + (long)zi * sBi;
    C += (long)zo * sCo + (long)zi * sCi;

    const int m0  = blockIdx.y * BM;
    const int n0  = blockIdx.x * BN;
    const int tid = threadIdx.x;
    const int wid = tid >> 5, lane = tid & 31;
    const int gid = lane >> 2, tig = lane & 3;
    const int wm  = wid / WGN, wn = wid % WGN;

    const uint32_t sb = smem_u32(sm);
    const int T = K / BK;
    const int crow = tid >> 3;               // 0..31 row group base
    const int ccol = (tid & 7) * 4;

    const float* Abase = A + (long)m0 * lda;
    const float* Bbase = B + (long)n0 * ldb;

#define COPY_TILE(KT, ST) do {                                                  \
        const uint32_t abase = sb + (uint32_t)(ST) * (ASZ + BSZ) * 4u;          \
        const uint32_t bbase = abase + ASZ * 4u;                                \
        const float* Ag = Abase + (KT) * BK;                                    \
        const float* Bg = Bbase + (KT) * BK;                                    \
        _Pragma("unroll")                                                       \
        for (int i = 0; i < 4; i++) {                                           \
            int row = crow + 32*i;                                              \
            cpasync16(abase + (uint32_t)(row*PAD + ccol)*4, Ag + (long)row*lda + ccol); \
        }                                                                       \
        _Pragma("unroll")                                                       \
        for (int i = 0; i < BN/32; i++) {                                       \
            int row = crow + 32*i;                                              \
            cpasync16(bbase + (uint32_t)(row*PAD + ccol)*4, Bg + (long)row*ldb + ccol); \
        }                                                                       \
        asm volatile("cp.async.commit_group;" ::: "memory");                    \
    } while (0)

    COPY_TILE(0, 0);
    COPY_TILE(1, 1);

    float cacc[MT][NT][4];
#pragma unroll
    for (int mt = 0; mt < MT; mt++)
#pragma unroll
        for (int nt = 0; nt < NT; nt++)
#pragma unroll
            for (int r = 0; r < 4; r++) cacc[mt][nt][r] = 0.f;

    for (int kt = 0; kt < T; kt++) {
        if (kt + 1 < T) asm volatile("cp.async.wait_group 1;" ::: "memory");
        else            asm volatile("cp.async.wait_group 0;" ::: "memory");
        __syncthreads();
        const uint32_t* As = sm + (kt & 1) * (ASZ + BSZ);
        const uint32_t* Bs = As + ASZ;

#pragma unroll
        for (int ks = 0; ks < 4; ks++) {
            uint32_t af[MT][4], bf[NT][2];
#pragma unroll
            for (int mt = 0; mt < MT; mt++) {
                const uint32_t* p = &As[(wm*WM + mt*16 + gid) * PAD + ks*8 + tig];
                af[mt][0] = p[0];
                af[mt][1] = p[8*PAD];
                af[mt][2] = p[4];
                af[mt][3] = p[8*PAD + 4];
            }
#pragma unroll
            for (int nt = 0; nt < NT; nt++) {
                const uint32_t* p = &Bs[(wn*WN + nt*8 + gid) * PAD + ks*8 + tig];
                bf[nt][0] = p[0];
                bf[nt][1] = p[4];
            }
#pragma unroll
            for (int mt = 0; mt < MT; mt++)
#pragma unroll
                for (int nt = 0; nt < NT; nt++)
                    mma1688(cacc[mt][nt], af[mt], bf[nt]);
        }
        __syncthreads();
        if (kt + 2 < T) COPY_TILE(kt + 2, kt & 1);
    }
#undef COPY_TILE

    if (STATS) {
        float s = 0.f, ss = 0.f;
#pragma unroll
        for (int mt = 0; mt < MT; mt++)
#pragma unroll
            for (int nt = 0; nt < NT; nt++)
#pragma unroll
                for (int r = 0; r < 4; r++) {
                    float v = cacc[mt][nt][r];
                    s += v; ss = fmaf(v, v, ss);
                }
        __shared__ float reds[256], redq[256];
        reds[tid] = s; redq[tid] = ss;
        __syncthreads();
        for (int o = 128; o > 0; o >>= 1) {
            if (tid < o) { reds[tid] += reds[tid+o]; redq[tid] += redq[tid+o]; }
            __syncthreads();
        }
        if (tid == 0) {
            int nblk  = gridDim.x * gridDim.y;
            int blkId = blockIdx.y * gridDim.x + blockIdx.x;
            long idx  = ((long)z * nblk + blkId) * 2;
            part[idx] = reds[0]; part[idx+1] = redq[0];
        }
    }

#pragma unroll
    for (int mt = 0; mt < MT; mt++) {
        const int row = m0 + wm*WM + mt*16 + gid;
#pragma unroll
        for (int nt = 0; nt < NT; nt++) {
            const int col = n0 + wn*WN + nt*8 + tig*2;
            float2 v0 = make_float2(cacc[mt][nt][0], cacc[mt][nt][1]);
            float2 v1 = make_float2(cacc[mt][nt][2], cacc[mt][nt][3]);
            if (RND) {
                v0.x = tf32rnf(v0.x); v0.y = tf32rnf(v0.y);
                v1.x = tf32rnf(v1.x); v1.y = tf32rnf(v1.y);
            }
            *(float2*)&C[(long)row * ldc + col]       = v0;
            *(float2*)&C[(long)(row + 8) * ldc + col] = v1;
        }
    }
}

// ===========================================================================
// Flash attention: grid (8 qt, 48 z=(s,b,h), 2 kv-half), 256 thr, 2 CTA/SM.
// ===========================================================================
__global__ __launch_bounds__(256, 2)
void flash_attn2(const float* __restrict__ QB3, const float* __restrict__ KM,
                 const float* __restrict__ VMt, const float* __restrict__ SCALE,
                 float* __restrict__ PO, float* __restrict__ ML)
{
    extern __shared__ uint32_t fsm[];    // Ks[2][64*68], Vs[2][64*68]
    const int z  = blockIdx.y;
    const int s  = z >> 4, b = (z >> 3) & 1, h = z & 7;
    const int qt = blockIdx.x, half = blockIdx.z;
    const float sc = SCALE[z];

    const int tid = threadIdx.x, wid = tid >> 5, lane = tid & 31;
    const int gid = lane >> 2, tig = lane & 3;

    const uint32_t* Qg = (const uint32_t*)QB3 + (long)s*1048576
                       + ((long)(b*1024 + qt*128))*512 + h*64;
    const float* Kg = KM  + ((long)(b*3072 + half*1536))*512 + h*64;
    const float* Vg = VMt + ((long)(b*512 + h*64))*3072 + half*1536;

    uint32_t qf[8][4];
    {
        const uint32_t* q0 = Qg + (long)(wid*16 + gid)*512;
        const uint32_t* q1 = q0 + 8*512;
#pragma unroll
        for (int ks = 0; ks < 8; ks++) {
            qf[ks][0] = q0[ks*8 + tig];
            qf[ks][1] = q1[ks*8 + tig];
            qf[ks][2] = q0[ks*8 + tig + 4];
            qf[ks][3] = q1[ks*8 + tig + 4];
        }
    }

    const uint32_t sbase = smem_u32(fsm);
    auto copy_tile = [&](int kt, int buf) {
        const float* ksrc = Kg + (long)kt * 64 * 512;
        const float* vsrc = Vg + kt * 64;
        const uint32_t kdst = sbase + buf * 17408u;
        const uint32_t vdst = sbase + 34816u + buf * 17408u;
#pragma unroll
        for (int i = 0; i < 4; i++) {
            int c = i*256 + tid;
            int row = c >> 4, col = (c & 15) * 4;
            cpasync16(kdst + (uint32_t)(row*68 + col)*4, ksrc + (long)row*512 + col);
            cpasync16(vdst + (uint32_t)(row*68 + col)*4, vsrc + (long)row*3072 + col);
        }
        asm volatile("cp.async.commit_group;" ::: "memory");
    };

    copy_tile(0, 0);
    copy_tile(1, 1);

    float m0 = -1e30f, m1 = -1e30f, l0 = 0.f, l1 = 0.f;
    float o[8][4];
#pragma unroll
    for (int nt = 0; nt < 8; nt++)
#pragma unroll
        for (int r = 0; r < 4; r++) o[nt][r] = 0.f;

    const int srcA = gid*4 + (tig >> 1);
    const int srcB = srcA + 2;
    const bool odd = tig & 1;

    for (int kt = 0; kt < 24; kt++) {
        if (kt + 1 < 24) asm volatile("cp.async.wait_group 1;" ::: "memory");
        else             asm volatile("cp.async.wait_group 0;" ::: "memory");
        __syncthreads();
        const uint32_t* Ks = fsm + (kt & 1) * 4352;
        const uint32_t* Vs = fsm + 8704 + (kt & 1) * 4352;

        float sacc[8][4];
#pragma unroll
        for (int nt = 0; nt < 8; nt++)
#pragma unroll
            for (int r = 0; r < 4; r++) sacc[nt][r] = 0.f;
#pragma unroll
        for (int ks = 0; ks < 8; ks++) {
#pragma unroll
            for (int nt = 0; nt < 8; nt++) {
                uint32_t bf[2];
                const uint32_t* bp = Ks + (nt*8 + gid)*68 + ks*8 + tig;
                bf[0] = bp[0]; bf[1] = bp[4];
                mma1688(sacc[nt], qf[ks], bf);
            }
        }
        float t0 = -1e30f, t1 = -1e30f;
#pragma unroll
        for (int nt = 0; nt < 8; nt++) {
            t0 = fmaxf(t0, fmaxf(sacc[nt][0], sacc[nt][1]));
            t1 = fmaxf(t1, fmaxf(sacc[nt][2], sacc[nt][3]));
        }
        t0 = fmaxf(t0, __shfl_xor_sync(0xffffffffu, t0, 1));
        t0 = fmaxf(t0, __shfl_xor_sync(0xffffffffu, t0, 2));
        t1 = fmaxf(t1, __shfl_xor_sync(0xffffffffu, t1, 1));
        t1 = fmaxf(t1, __shfl_xor_sync(0xffffffffu, t1, 2));
        float nm0 = fmaxf(m0, sc*t0), nm1 = fmaxf(m1, sc*t1);
        float f0 = __expf(m0 - nm0), f1 = __expf(m1 - nm1);
        float s0 = 0.f, s1 = 0.f;
#pragma unroll
        for (int nt = 0; nt < 8; nt++) {
            sacc[nt][0] = __expf(fmaf(sc, sacc[nt][0], -nm0));
            sacc[nt][1] = __expf(fmaf(sc, sacc[nt][1], -nm0));
            sacc[nt][2] = __expf(fmaf(sc, sacc[nt][2], -nm1));
            sacc[nt][3] = __expf(fmaf(sc, sacc[nt][3], -nm1));
            s0 += sacc[nt][0] + sacc[nt][1];
            s1 += sacc[nt][2] + sacc[nt][3];
        }
        s0 += __shfl_xor_sync(0xffffffffu, s0, 1);
        s0 += __shfl_xor_sync(0xffffffffu, s0, 2);
        s1 += __shfl_xor_sync(0xffffffffu, s1, 1);
        s1 += __shfl_xor_sync(0xffffffffu, s1, 2);
        l0 = l0*f0 + s0; l1 = l1*f1 + s1;
        m0 = nm0; m1 = nm1;
#pragma unroll
        for (int nt = 0; nt < 8; nt++) {
            o[nt][0] *= f0; o[nt][1] *= f0; o[nt][2] *= f1; o[nt][3] *= f1;
        }
#pragma unroll
        for (int ks = 0; ks < 8; ks++) {
            float v0 = __shfl_sync(0xffffffffu, sacc[ks][0], srcA);
            float v1 = __shfl_sync(0xffffffffu, sacc[ks][1], srcA);
            float v2 = __shfl_sync(0xffffffffu, sacc[ks][2], srcA);
            float v3 = __shfl_sync(0xffffffffu, sacc[ks][3], srcA);
            float w0 = __shfl_sync(0xffffffffu, sacc[ks][0], srcB);
            float w1 = __shfl_sync(0xffffffffu, sacc[ks][1], srcB);
            float w2 = __shfl_sync(0xffffffffu, sacc[ks][2], srcB);
            float w3 = __shfl_sync(0xffffffffu, sacc[ks][3], srcB);
            uint32_t af[4];
            af[0] = tf32rn(odd ? v1 : v0);
            af[1] = tf32rn(odd ? v3 : v2);
            af[2] = tf32rn(odd ? w1 : w0);
            af[3] = tf32rn(odd ? w3 : w2);
#pragma unroll
            for (int nt = 0; nt < 8; nt++) {
                uint32_t bf[2];
                const uint32_t* bp = Vs + (nt*8 + gid)*68 + ks*8 + tig;
                bf[0] = bp[0]; bf[1] = bp[4];
                mma1688(o[nt], af, bf);
            }
        }
        __syncthreads();
        if (kt + 2 < 24) copy_tile(kt + 2, kt & 1);
    }

    const long rowg = ((long)(half*48 + z))*1024 + qt*128 + wid*16 + gid;
    float* po0 = PO + rowg*64;
    float* po1 = PO + (rowg + 8)*64;
#pragma unroll
    for (int nt = 0; nt < 8; nt++) {
        *(float2*)(po0 + nt*8 + 2*tig) = make_float2(o[nt][0], o[nt][1]);
        *(float2*)(po1 + nt*8 + 2*tig) = make_float2(o[nt][2], o[nt][3]);
    }
    if (tig == 0) {
        ML[rowg*2]       = m0; ML[rowg*2 + 1]       = l0;
        ML[(rowg+8)*2]   = m1; ML[(rowg+8)*2 + 1]   = l1;
    }
}

// merge two kv-halves; output rounded to tf32 (consumed by output-proj GEMM)
__global__ __launch_bounds__(256)
void flash_merge(const float* __restrict__ PO, const float* __restrict__ ML,
                 float* __restrict__ CTXB3)
{
    const int z = blockIdx.y;
    const int s = z >> 4, b = (z >> 3) & 1, h = z & 7;
    const int row = blockIdx.x*128 + (threadIdx.x >> 1);
    const int cof = (threadIdx.x & 1) * 32;

    const long rA = (long)z*1024 + row;
    const long rB = (long)(48 + z)*1024 + row;
    float ma = ML[rA*2], la = ML[rA*2+1];
    float mb = ML[rB*2], lb = ML[rB*2+1];
    float m  = fmaxf(ma, mb);
    float fa = __expf(ma - m), fb = __expf(mb - m);
    float inv = 1.0f / (la*fa + lb*fb);
    fa *= inv; fb *= inv;

    const float* pa = PO + rA*64 + cof;
    const float* pb = PO + rB*64 + cof;
    float* dst = CTXB3 + (long)s*1048576 + ((long)(b*1024 + row))*512 + h*64 + cof;
#pragma unroll
    for (int i = 0; i < 8; i++) {
        float4 va = *(const float4*)(pa + i*4);
        float4 vb = *(const float4*)(pb + i*4);
        float4 r;
        r.x = tf32rnf(va.x*fa + vb.x*fb); r.y = tf32rnf(va.y*fa + vb.y*fb);
        r.z = tf32rnf(va.z*fa + vb.z*fb); r.w = tf32rnf(va.w*fa + vb.w*fb);
        *(float4*)(dst + i*4) = r;
    }
}

// ---------------------------------------------------------------------------
// scale_gram
// ---------------------------------------------------------------------------
__global__ __launch_bounds__(256)
void scale_gram(const float* __restrict__ QBt3, const float* __restrict__ KMt,
                const float* __restrict__ GQ, const float* __restrict__ GK,
                float* __restrict__ SCALE)
{
    const int z = blockIdx.x;
    const int s = z >> 4, bh = z & 15;
    const float* Qt = QBt3 + (long)s*1048576 + (long)bh*65536;
    const float* Kt = KMt + (long)bh*196608;
    __shared__ float sq[64], sk[64], red[256];
    const int tid = threadIdx.x;
    {
        int i = tid >> 2, part = tid & 3;
        float su = 0.f;
        for (int m = part; m < 1024; m += 4) su += Qt[(long)i*1024 + m];
        su += __shfl_xor_sync(0xffffffffu, su, 1);
        su += __shfl_xor_sync(0xffffffffu, su, 2);
        if (part == 0) sq[i] = su;
        float t = 0.f;
        for (int m = part; m < 3072; m += 4) t += Kt[(long)i*3072 + m];
        t += __shfl_xor_sync(0xffffffffu, t, 1);
        t += __shfl_xor_sync(0xffffffffu, t, 2);
        if (part == 0) sk[i] = t;
    }
    __syncthreads();
    float a = (tid < 64) ? sq[tid]*sk[tid] : 0.f;
    red[tid] = a;
    __syncthreads();
    for (int o = 128; o > 0; o >>= 1) {
        if (tid < o) red[tid] += red[tid+o];
        __syncthreads();
    }
    float sx = red[0];
    __syncthreads();
    const float* gq = GQ + (long)z*8192;
    const float* gk = GK + (long)bh*8192;
    float a2 = 0.f;
    for (int i = tid; i < 4096; i += 256) a2 = fmaf(gq[i], gk[i], a2);
    red[tid] = a2;
    __syncthreads();
    for (int o = 128; o > 0; o >>= 1) {
        if (tid < o) red[tid] += red[tid+o];
        __syncthreads();
    }
    if (tid == 0) {
        const float cnt = 1024.0f * 3072.0f;
        float mu  = sx / cnt;
        float var = red[0] / cnt - mu*mu;
        SCALE[z]  = rsqrtf(fmaxf(var, 0.f) + 1e-5f);
    }
}

// ---------------------------------------------------------------------------
// stats_final / softmax_rows (rounds output) / kvs_transpose
// ---------------------------------------------------------------------------
__global__ __launch_bounds__(256)
void stats_final(const float* __restrict__ part, int nblk, long perZ,
                 float* __restrict__ scale)
{
    int z = blockIdx.x;
    float s = 0.f, ss = 0.f;
    for (int i = threadIdx.x; i < nblk; i += 256) {
        s  += part[((long)z*nblk + i)*2];
        ss += part[((long)z*nblk + i)*2 + 1];
    }
    __shared__ float a[256], b2[256];
    a[threadIdx.x] = s; b2[threadIdx.x] = ss;
    __syncthreads();
    for (int o = 128; o > 0; o >>= 1) {
        if (threadIdx.x < o) { a[threadIdx.x] += a[threadIdx.x+o]; b2[threadIdx.x] += b2[threadIdx.x+o]; }
        __syncthreads();
    }
    if (threadIdx.x == 0) {
        float mu  = a[0] / (float)perZ;
        float var = b2[0] / (float)perZ - mu*mu;
        scale[z]  = rsqrtf(fmaxf(var, 0.f) + 1e-5f);
    }
}

template<int PER>
__global__ __launch_bounds__(256)
void softmax_rows(float* __restrict__ x, int L,
                  const float* __restrict__ scale, int rowsPerScale)
{
    long row = blockIdx.x;
    float s  = scale[row / rowsPerScale];
    float* p = x + row * (long)L;

    float v[PER];
    float mx = -1e30f;
#pragma unroll
    for (int i = 0; i < PER; i++) {
        v[i] = p[threadIdx.x + i*256] * s;
        mx = fmaxf(mx, v[i]);
    }
    __shared__ float sh[8];
    for (int o = 16; o > 0; o >>= 1) mx = fmaxf(mx, __shfl_xor_sync(0xffffffffu, mx, o));
    if ((threadIdx.x & 31) == 0) sh[threadIdx.x >> 5] = mx;
    __syncthreads();
    mx = sh[0];
#pragma unroll
    for (int i = 1; i < 8; i++) mx = fmaxf(mx, sh[i]);

    float sum = 0.f;
#pragma unroll
    for (int i = 0; i < PER; i++) { v[i] = __expf(v[i] - mx); sum += v[i]; }
    __shared__ float sh2[8];
    for (int o = 16; o > 0; o >>= 1) sum += __shfl_xor_sync(0xffffffffu, sum, o);
    if ((threadIdx.x & 31) == 0) sh2[threadIdx.x >> 5] = sum;
    __syncthreads();
    sum = 0.f;
#pragma unroll
    for (int i = 0; i < 8; i++) sum += sh2[i];

    float inv = 1.0f / sum;
#pragma unroll
    for (int i = 0; i < PER; i++) p[threadIdx.x + i*256] = tf32rnf(v[i] * inv);
}

__global__ void kvs_transpose(const float* __restrict__ ctxc, float* __restrict__ kvs)
{
    int z = blockIdx.z;
    int b = z / 3, j = z % 3;
    const float* src = ctxc + (long)b*1536*1024 + (long)j*512*1024;
    float*       dst = kvs  + (long)b*3072*512  + (long)j*1024*512;

    __shared__ float t[32][33];
    int n0 = blockIdx.x*32, e0 = blockIdx.y*32;
    int tx = threadIdx.x, ty = threadIdx.y;
#pragma unroll
    for (int i = 0; i < 32; i += 8)
        t[ty+i][tx] = src[(long)(e0+ty+i)*1024 + (n0+tx)];
    __syncthreads();
#pragma unroll
    for (int i = 0; i < 32; i += 8)
        dst[(long)(n0+ty+i)*512 + (e0+tx)] = t[tx][ty+i];
}

// ---------------------------------------------------------------------------
// Host orchestration (graph-capturable: kernel launches only)
// ---------------------------------------------------------------------------
static constexpr int GEMM_SMEM128 = 2 * (128*36 + 128*36) * 4;   // 73728
static constexpr int GEMM_SMEM64  = 2 * (128*36 +  64*36) * 4;   // 55296
static constexpr int FLASH_SMEM   = 4 * 64 * 68 * 4;             // 69632

extern "C" void kernel_launch(void* const* d_in, const int* in_sizes, int n_in,
                              void* d_out, int out_size)
{
    const float* emb[3] = {(const float*)d_in[0], (const float*)d_in[1], (const float*)d_in[2]};
    const float* embC   = (const float*)d_in[3];
    const float* Wq[3]  = {(const float*)d_in[4], (const float*)d_in[5], (const float*)d_in[6]};
    const float* Wk     = (const float*)d_in[7];
    const float* Wv     = (const float*)d_in[8];
    const float* WqC    = (const float*)d_in[9];
    const float* WkC    = (const float*)d_in[10];
    const float* WvC    = (const float*)d_in[11];
    const float* Wo[3]  = {(const float*)d_in[12], (const float*)d_in[13], (const float*)d_in[14]};
    float* out = (float*)d_out;

    float *QCt,*KCt,*VC,*ATTC,*CTXC,*KVS,*KM,*VMt,*QB3,*QBt3,*KMt,*GQ,*GK,*PO,*ML,*CTXB3,*PART,*SCALE;
    float *embCr,*embr,*WqCr,*WkCr,*WvCr,*Wkr,*Wvr,*Wqr,*Wor;
    cudaGetSymbolAddress((void**)&QCt,  g_QCt);
    cudaGetSymbolAddress((void**)&KCt,  g_KCt);
    cudaGetSymbolAddress((void**)&VC,   g_VC);
    cudaGetSymbolAddress((void**)&ATTC, g_ATTC);
    cudaGetSymbolAddress((void**)&CTXC, g_CTXC);
    cudaGetSymbolAddress((void**)&KVS,  g_KVS);
    cudaGetSymbolAddress((void**)&KM,   g_KM);
    cudaGetSymbolAddress((void**)&VMt,  g_VMt);
    cudaGetSymbolAddress((void**)&QB3,  g_QB3);
    cudaGetSymbolAddress((void**)&QBt3, g_QBt3);
    cudaGetSymbolAddress((void**)&KMt,  g_KMt);
    cudaGetSymbolAddress((void**)&GQ,   g_GQ);
    cudaGetSymbolAddress((void**)&GK,   g_GK);
    cudaGetSymbolAddress((void**)&PO,   g_PO);
    cudaGetSymbolAddress((void**)&ML,   g_ML);
    cudaGetSymbolAddress((void**)&CTXB3,g_CTXB3);
    cudaGetSymbolAddress((void**)&PART, g_PART);
    cudaGetSymbolAddress((void**)&SCALE,g_SCALE);
    cudaGetSymbolAddress((void**)&embCr,g_embCr);
    cudaGetSymbolAddress((void**)&embr, g_embr);
    cudaGetSymbolAddress((void**)&WqCr, g_WqCr);
    cudaGetSymbolAddress((void**)&WkCr, g_WkCr);
    cudaGetSymbolAddress((void**)&WvCr, g_WvCr);
    cudaGetSymbolAddress((void**)&Wkr,  g_Wkr);
    cudaGetSymbolAddress((void**)&Wvr,  g_Wvr);
    cudaGetSymbolAddress((void**)&Wqr,  g_Wqr);
    cudaGetSymbolAddress((void**)&Wor,  g_Wor);

    cudaFuncSetAttribute((const void*)mma_gemm<128,false,false>, cudaFuncAttributeMaxDynamicSharedMemorySize, GEMM_SMEM128);
    cudaFuncSetAttribute((const void*)mma_gemm<128,true ,false>, cudaFuncAttributeMaxDynamicSharedMemorySize, GEMM_SMEM128);
    cudaFuncSetAttribute((const void*)mma_gemm<128,false,true >, cudaFuncAttributeMaxDynamicSharedMemorySize, GEMM_SMEM128);
    cudaFuncSetAttribute((const void*)mma_gemm<64 ,false,false>, cudaFuncAttributeMaxDynamicSharedMemorySize, GEMM_SMEM64);
    cudaFuncSetAttribute((const void*)flash_attn2, cudaFuncAttributeMaxDynamicSharedMemorySize, FLASH_SMEM);

    // ---- 0) pre-round all external inputs to tf32 ----
    {
        RoundJobs j;
        j.src[0]  = (const float4*)embC;   j.dst[0]  = (float4*)embCr;            j.n4[0]  = 2*1024*1536/4;
        j.src[1]  = (const float4*)emb[0]; j.dst[1]  = (float4*)embr;             j.n4[1]  = 1048576/4;
        j.src[2]  = (const float4*)emb[1]; j.dst[2]  = (float4*)(embr+1048576);   j.n4[2]  = 1048576/4;
        j.src[3]  = (const float4*)emb[2]; j.dst[3]  = (float4*)(embr+2097152);   j.n4[3]  = 1048576/4;
        j.src[4]  = (const float4*)WqC;    j.dst[4]  = (float4*)WqCr;             j.n4[4]  = 1536*1536/4;
        j.src[5]  = (const float4*)WkC;    j.dst[5]  = (float4*)WkCr;             j.n4[5]  = 1536*1536/4;
        j.src[6]  = (const float4*)WvC;    j.dst[6]  = (float4*)WvCr;             j.n4[6]  = 1536*1536/4;
        j.src[7]  = (const float4*)Wk;     j.dst[7]  = (float4*)Wkr;              j.n4[7]  = 512*512/4;
        j.src[8]  = (const float4*)Wv;     j.dst[8]  = (float4*)Wvr;              j.n4[8]  = 512*512/4;
        j.src[9]  = (const float4*)Wq[0];  j.dst[9]  = (float4*)Wqr;              j.n4[9]  = 512*512/4;
        j.src[10] = (const float4*)Wq[1];  j.dst[10] = (float4*)(Wqr+262144);     j.n4[10] = 512*512/4;
        j.src[11] = (const float4*)Wq[2];  j.dst[11] = (float4*)(Wqr+524288);     j.n4[11] = 512*512/4;
        j.src[12] = (const float4*)Wo[0];  j.dst[12] = (float4*)Wor;              j.n4[12] = 512*512/4;
        j.src[13] = (const float4*)Wo[1];  j.dst[13] = (float4*)(Wor+262144);     j.n4[13] = 512*512/4;
        j.src[14] = (const float4*)Wo[2];  j.dst[14] = (float4*)(Wor+524288);     j.n4[14] = 512*512/4;
        round_many<<<dim3(96,15),256>>>(j);
    }

    // ---- 1) channel projections (outputs rounded: feed further GEMMs) ----
    mma_gemm<128,false,true><<<dim3(8,12,2),256,GEMM_SMEM128>>>(WqCr, embCr, QCt, 1536, 1536,1536,1024,
        0,0, 1572864,0, 1572864,0, 1, nullptr);
    mma_gemm<128,false,true><<<dim3(8,12,2),256,GEMM_SMEM128>>>(WkCr, embCr, KCt, 1536, 1536,1536,1024,
        0,0, 1572864,0, 1572864,0, 1, nullptr);
    mma_gemm<128,false,true><<<dim3(12,16,1),256,GEMM_SMEM128>>>(embCr, WvCr, VC, 1536, 1536,1536,1536,
        0,0, 0,0, 0,0, 1, nullptr);

    // ---- 2) channel attention (stats fused; raw output, softmax rounds) ----
    mma_gemm<128,true,false><<<dim3(12,12,2),256,GEMM_SMEM128>>>(QCt, KCt, ATTC, 1024, 1024,1024,1536,
        1572864,0, 1572864,0, 2359296,0, 1, PART);
    stats_final<<<2,256>>>(PART, 144, 2359296L, SCALE);
    softmax_rows<6><<<2*1536,256>>>(ATTC, 1536, SCALE, 1536);

    mma_gemm<128,false,true><<<dim3(8,12,2),256,GEMM_SMEM128>>>(ATTC, VC, CTXC, 1536, 1536,1536,1024,
        2359296,0, 1572864,0, 1572864,0, 1, nullptr);

    // ---- 3) KV_S build + K/V projections ----
    kvs_transpose<<<dim3(32,16,6),dim3(32,8)>>>(CTXC, KVS);
    mma_gemm<128,false,true><<<dim3(4,48,1),256,GEMM_SMEM128>>>(KVS, Wkr, KM, 512, 512,512,512,
        0,0, 0,0, 0,0, 1, nullptr);
    mma_gemm<128,false,true><<<dim3(24,4,2),256,GEMM_SMEM128>>>(Wvr, KVS, VMt, 512, 512,512,3072,
        0,0, 1572864,0, 1572864,0, 1, nullptr);
    mma_gemm<128,false,true><<<dim3(24,4,2),256,GEMM_SMEM128>>>(Wkr, KVS, KMt, 512, 512,512,3072,
        0,0, 1572864,0, 1572864,0, 1, nullptr);

    // ---- GK[z]=K_h^T K_h ----
    mma_gemm<64,false,false><<<dim3(1,1,16),256,GEMM_SMEM64>>>(KMt, KMt, GK, 3072, 3072,3072,64,
        1572864,196608, 1572864,196608, 65536,8192, 8, nullptr);

    // ---- 4) Q projections (both orientations) ----
    for (int s = 0; s < 3; s++) {
        mma_gemm<128,false,true><<<dim3(4,16,1),256,GEMM_SMEM128>>>(embr + (long)s*1048576,
            Wqr + (long)s*262144, QB3 + (long)s*1048576,
            512, 512,512,512, 0,0, 0,0, 0,0, 1, nullptr);
        mma_gemm<128,false,true><<<dim3(8,4,2),256,GEMM_SMEM128>>>(Wqr + (long)s*262144,
            embr + (long)s*1048576, QBt3 + (long)s*1048576,
            512, 512,512,1024, 0,0, 524288,0, 524288,0, 1, nullptr);
    }
    mma_gemm<64,false,false><<<dim3(1,1,48),256,GEMM_SMEM64>>>(QBt3, QBt3, GQ, 1024, 1024,1024,64,
        1048576,65536, 1048576,65536, 131072,8192, 16, nullptr);
    scale_gram<<<48,256>>>(QBt3, KMt, GQ, GK, SCALE);

    // ---- 5) batched flash attention + merge ----
    flash_attn2<<<dim3(8,48,2),256,FLASH_SMEM>>>(QB3, KM, VMt, SCALE, PO, ML);
    flash_merge<<<dim3(8,48),256>>>(PO, ML, CTXB3);

    // ---- 6) output projections ----
    for (int s = 0; s < 3; s++)
        mma_gemm<128,false,false><<<dim3(4,16,1),256,GEMM_SMEM128>>>(CTXB3 + (long)s*1048576,
            Wor + (long)s*262144, out + (long)s*1048576,
            512, 512,512,512, 0,0, 0,0, 0,0, 1, nullptr);
}

// round 15
// speedup vs baseline: 1.0074x; 1.0074x over previous
#include <cuda_runtime.h>
#include <cstdint>

// ===========================================================================
// Problem: B=2, N=1024, E=512, H=8, d=64, KVC=1536, 3N=3072
// All MMA operands pre-rounded to tf32 (rna) in memory; GEMMs use a 2-stage
// cp.async pipeline with no in-loop conversion. Spatial attention flash-fused
// (split-KV, 3 streams batched); instance-norm variance via Gram identities:
//   sum(QK^T) = (sum q)·(sum k),  sum((QK^T)^2) = <Q^T Q, K^T K>.
// ===========================================================================

// ------------------------- scratch (__device__ globals) -------------------
__device__ float g_QCt [2*1536*1024];
__device__ float g_KCt [2*1536*1024];
__device__ float g_VC  [2*1024*1536];
__device__ float g_ATTC[2*1536*1536];
__device__ float g_CTXC[2*1536*1024];
__device__ float g_KVS [2*3072*512];
__device__ float g_KM  [2*3072*512];
__device__ float g_VMt [2*512*3072];
__device__ float g_KMt [2*512*3072 + 128*3072];
__device__ float g_QB3 [3*2*1024*512];
__device__ float g_QBt3[3*2*512*1024 + 64*1024];
__device__ float g_GQ  [48*128*64];
__device__ float g_GK  [16*128*64];
__device__ float g_PO  [2*48*1024*64];
__device__ float g_ML  [2*48*1024*2];
__device__ float g_CTXB3[3*2*1024*512];
__device__ float g_PART[16*256*2];
__device__ float g_SCALE[48];
// rounded copies of external inputs
__device__ float g_embCr[2*1024*1536];
__device__ float g_embr [3*2*1024*512];
__device__ float g_WqCr [1536*1536];
__device__ float g_WkCr [1536*1536];
__device__ float g_WvCr [1536*1536];
__device__ float g_Wkr  [512*512];
__device__ float g_Wvr  [512*512];
__device__ float g_Wqr  [3*512*512];
__device__ float g_Wor  [3*512*512];

// ------------------------- helpers ----------------------------------------
__device__ __forceinline__ uint32_t tf32rn(float x) {
    uint32_t r;
    asm("cvt.rna.tf32.f32 %0, %1;" : "=r"(r) : "f"(x));
    return r;
}
__device__ __forceinline__ float tf32rnf(float x) { return __uint_as_float(tf32rn(x)); }
__device__ __forceinline__ uint32_t smem_u32(const void* p) {
    uint32_t a;
    asm("{ .reg .u64 t; cvta.to.shared.u64 t, %1; cvt.u32.u64 %0, t; }" : "=r"(a) : "l"(p));
    return a;
}
__device__ __forceinline__ void cpasync16(uint32_t saddr, const void* g) {
    asm volatile("cp.async.cg.shared.global [%0], [%1], 16;" :: "r"(saddr), "l"(g) : "memory");
}
__device__ __forceinline__ void mma1688(float* c, const uint32_t* a, const uint32_t* b) {
    asm volatile(
        "mma.sync.aligned.m16n8k8.row.col.f32.tf32.tf32.f32 "
        "{%0,%1,%2,%3}, {%4,%5,%6,%7}, {%8,%9}, {%0,%1,%2,%3};"
        : "+f"(c[0]), "+f"(c[1]), "+f"(c[2]), "+f"(c[3])
        : "r"(a[0]), "r"(a[1]), "r"(a[2]), "r"(a[3]), "r"(b[0]), "r"(b[1]));
}

// ---------------------------------------------------------------------------
// round_many: batched elementwise tf32 rounding of external inputs
// ---------------------------------------------------------------------------
struct RoundJobs {
    const float4* src[15];
    float4*       dst[15];
    int           n4[15];
};
__global__ __launch_bounds__(256)
void round_many(RoundJobs j)
{
    const int b = blockIdx.y;
    const int n4 = j.n4[b];
    const float4* s = j.src[b];
    float4* d = j.dst[b];
    for (int i = blockIdx.x*256 + threadIdx.x; i < n4; i += gridDim.x*256) {
        float4 v = s[i];
        v.x = tf32rnf(v.x); v.y = tf32rnf(v.y);
        v.z = tf32rnf(v.z); v.w = tf32rnf(v.w);
        d[i] = v;
    }
}

// ===========================================================================
// cp.async tensor-core GEMM:  C[m,n] = sum_k A[m*lda+k] * B[n*ldb+k]
//   Operands MUST be tf32-exact in memory. BM=128, BK=32, BN in {64,128}.
//   2-stage double buffer. K/BK >= 2. z-batch as before.
// ===========================================================================
template<int BN, bool STATS, bool RND>
__global__ __launch_bounds__(256)
void mma_gemm(const float* __restrict__ A, const float* __restrict__ B, float* __restrict__ C,
              int K, int lda, int ldb, int ldc,
              long sAo, long sAi, long sBo, long sBi, long sCo, long sCi,
              int innerB, float* __restrict__ part)
{
    constexpr int BM  = 128, BK = 32, PAD = 36;
    constexpr int ASZ = BM * PAD;            // uint32 words
    constexpr int BSZ = BN * PAD;
    constexpr int WGN = (BN == 128) ? 4 : 2;
    constexpr int WM  = (BN == 128) ? 64 : 32;
    constexpr int WN  = 32;
    constexpr int MT  = WM / 16;
    constexpr int NT  = WN / 8;

    extern __shared__ uint32_t sm[];         // 2 stages x (ASZ + BSZ)

    const int z  = blockIdx.z;
    const int zo = z / innerB, zi = z % innerB;
    A += (long)zo * sAo + (long)zi * sAi;
    B += (long)zo * sBo + (long)zi * sBi;
    C += (long)zo * sCo + (long)zi * sCi;

    const int m0  = blockIdx.y * BM;
    const int n0  = blockIdx.x * BN;
    const int tid = threadIdx.x;
    const int wid = tid >> 5, lane = tid & 31;
    const int gid = lane >> 2, tig = lane & 3;
    const int wm  = wid / WGN, wn = wid % WGN;

    const uint32_t sb = smem_u32(sm);
    const int T = K / BK;
    const int crow = tid >> 3;               // 0..31 row group base
    const int ccol = (tid & 7) * 4;

    const float* Abase = A + (long)m0 * lda;
    const float* Bbase = B + (long)n0 * ldb;

#define COPY_TILE(KT, ST) do {                                                  \
        const uint32_t abase = sb + (uint32_t)(ST) * (ASZ + BSZ) * 4u;          \
        const uint32_t bbase = abase + ASZ * 4u;                                \
        const float* Ag = Abase + (KT) * BK;                                    \
        const float* Bg = Bbase + (KT) * BK;                                    \
        _Pragma("unroll")                                                       \
        for (int i = 0; i < 4; i++) {                                           \
            int row = crow + 32*i;                                              \
            cpasync16(abase + (uint32_t)(row*PAD + ccol)*4, Ag + (long)row*lda + ccol); \
        }                                                                       \
        _Pragma("unroll")                                                       \
        for (int i = 0; i < BN/32; i++) {                                       \
            int row = crow + 32*i;                                              \
            cpasync16(bbase + (uint32_t)(row*PAD + ccol)*4, Bg + (long)row*ldb + ccol); \
        }                                                                       \
        asm volatile("cp.async.commit_group;" ::: "memory");                    \
    } while (0)

    COPY_TILE(0, 0);
    COPY_TILE(1, 1);

    float cacc[MT][NT][4];
#pragma unroll
    for (int mt = 0; mt < MT; mt++)
#pragma unroll
        for (int nt = 0; nt < NT; nt++)
#pragma unroll
            for (int r = 0; r < 4; r++) cacc[mt][nt][r] = 0.f;

    for (int kt = 0; kt < T; kt++) {
        if (kt + 1 < T) asm volatile("cp.async.wait_group 1;" ::: "memory");
        else            asm volatile("cp.async.wait_group 0;" ::: "memory");
        __syncthreads();
        const uint32_t* As = sm + (kt & 1) * (ASZ + BSZ);
        const uint32_t* Bs = As + ASZ;

#pragma unroll
        for (int ks = 0; ks < 4; ks++) {
            uint32_t af[MT][4], bf[NT][2];
#pragma unroll
            for (int mt = 0; mt < MT; mt++) {
                const uint32_t* p = &As[(wm*WM + mt*16 + gid) * PAD + ks*8 + tig];
                af[mt][0] = p[0];
                af[mt][1] = p[8*PAD];
                af[mt][2] = p[4];
                af[mt][3] = p[8*PAD + 4];
            }
#pragma unroll
            for (int nt = 0; nt < NT; nt++) {
                const uint32_t* p = &Bs[(wn*WN + nt*8 + gid) * PAD + ks*8 + tig];
                bf[nt][0] = p[0];
                bf[nt][1] = p[4];
            }
#pragma unroll
            for (int mt = 0; mt < MT; mt++)
#pragma unroll
                for (int nt = 0; nt < NT; nt++)
                    mma1688(cacc[mt][nt], af[mt], bf[nt]);
        }
        __syncthreads();
        if (kt + 2 < T) COPY_TILE(kt + 2, kt & 1);
    }
#undef COPY_TILE

    if (STATS) {
        float s = 0.f, ss = 0.f;
#pragma unroll
        for (int mt = 0; mt < MT; mt++)
#pragma unroll
            for (int nt = 0; nt < NT; nt++)
#pragma unroll
                for (int r = 0; r < 4; r++) {
                    float v = cacc[mt][nt][r];
                    s += v; ss = fmaf(v, v, ss);
                }
        __shared__ float reds[256], redq[256];
        reds[tid] = s; redq[tid] = ss;
        __syncthreads();
        for (int o = 128; o > 0; o >>= 1) {
            if (tid < o) { reds[tid] += reds[tid+o]; redq[tid] += redq[tid+o]; }
            __syncthreads();
        }
        if (tid == 0) {
            int nblk  = gridDim.x * gridDim.y;
            int blkId = blockIdx.y * gridDim.x + blockIdx.x;
            long idx  = ((long)z * nblk + blkId) * 2;
            part[idx] = reds[0]; part[idx+1] = redq[0];
        }
    }

#pragma unroll
    for (int mt = 0; mt < MT; mt++) {
        const int row = m0 + wm*WM + mt*16 + gid;
#pragma unroll
        for (int nt = 0; nt < NT; nt++) {
            const int col = n0 + wn*WN + nt*8 + tig*2;
            float2 v0 = make_float2(cacc[mt][nt][0], cacc[mt][nt][1]);
            float2 v1 = make_float2(cacc[mt][nt][2], cacc[mt][nt][3]);
            if (RND) {
                v0.x = tf32rnf(v0.x); v0.y = tf32rnf(v0.y);
                v1.x = tf32rnf(v1.x); v1.y = tf32rnf(v1.y);
            }
            *(float2*)&C[(long)row * ldc + col]       = v0;
            *(float2*)&C[(long)(row + 8) * ldc + col] = v1;
        }
    }
}

// ===========================================================================
// Flash attention: grid (8 qt, 48 z=(s,b,h), 2 kv-half), 256 thr, 2 CTA/SM.
// ===========================================================================
__global__ __launch_bounds__(256, 2)
void flash_attn2(const float* __restrict__ QB3, const float* __restrict__ KM,
                 const float* __restrict__ VMt, const float* __restrict__ SCALE,
                 float* __restrict__ PO, float* __restrict__ ML)
{
    extern __shared__ uint32_t fsm[];    // Ks[2][64*68], Vs[2][64*68]
    const int z  = blockIdx.y;
    const int s  = z >> 4, b = (z >> 3) & 1, h = z & 7;
    const int qt = blockIdx.x, half = blockIdx.z;
    const float sc = SCALE[z];

    const int tid = threadIdx.x, wid = tid >> 5, lane = tid & 31;
    const int gid = lane >> 2, tig = lane & 3;

    const uint32_t* Qg = (const uint32_t*)QB3 + (long)s*1048576
                       + ((long)(b*1024 + qt*128))*512 + h*64;
    const float* Kg = KM  + ((long)(b*3072 + half*1536))*512 + h*64;
    const float* Vg = VMt + ((long)(b*512 + h*64))*3072 + half*1536;

    uint32_t qf[8][4];
    {
        const uint32_t* q0 = Qg + (long)(wid*16 + gid)*512;
        const uint32_t* q1 = q0 + 8*512;
#pragma unroll
        for (int ks = 0; ks < 8; ks++) {
            qf[ks][0] = q0[ks*8 + tig];
            qf[ks][1] = q1[ks*8 + tig];
            qf[ks][2] = q0[ks*8 + tig + 4];
            qf[ks][3] = q1[ks*8 + tig + 4];
        }
    }

    const uint32_t sbase = smem_u32(fsm);
    auto copy_tile = [&](int kt, int buf) {
        const float* ksrc = Kg + (long)kt * 64 * 512;
        const float* vsrc = Vg + kt * 64;
        const uint32_t kdst = sbase + buf * 17408u;
        const uint32_t vdst = sbase + 34816u + buf * 17408u;
#pragma unroll
        for (int i = 0; i < 4; i++) {
            int c = i*256 + tid;
            int row = c >> 4, col = (c & 15) * 4;
            cpasync16(kdst + (uint32_t)(row*68 + col)*4, ksrc + (long)row*512 + col);
            cpasync16(vdst + (uint32_t)(row*68 + col)*4, vsrc + (long)row*3072 + col);
        }
        asm volatile("cp.async.commit_group;" ::: "memory");
    };

    copy_tile(0, 0);
    copy_tile(1, 1);

    float m0 = -1e30f, m1 = -1e30f, l0 = 0.f, l1 = 0.f;
    float o[8][4];
#pragma unroll
    for (int nt = 0; nt < 8; nt++)
#pragma unroll
        for (int r = 0; r < 4; r++) o[nt][r] = 0.f;

    const int srcA = gid*4 + (tig >> 1);
    const int srcB = srcA + 2;
    const bool odd = tig & 1;

    for (int kt = 0; kt < 24; kt++) {
        if (kt + 1 < 24) asm volatile("cp.async.wait_group 1;" ::: "memory");
        else             asm volatile("cp.async.wait_group 0;" ::: "memory");
        __syncthreads();
        const uint32_t* Ks = fsm + (kt & 1) * 4352;
        const uint32_t* Vs = fsm + 8704 + (kt & 1) * 4352;

        float sacc[8][4];
#pragma unroll
        for (int nt = 0; nt < 8; nt++)
#pragma unroll
            for (int r = 0; r < 4; r++) sacc[nt][r] = 0.f;
#pragma unroll
        for (int ks = 0; ks < 8; ks++) {
#pragma unroll
            for (int nt = 0; nt < 8; nt++) {
                uint32_t bf[2];
                const uint32_t* bp = Ks + (nt*8 + gid)*68 + ks*8 + tig;
                bf[0] = bp[0]; bf[1] = bp[4];
                mma1688(sacc[nt], qf[ks], bf);
            }
        }
        float t0 = -1e30f, t1 = -1e30f;
#pragma unroll
        for (int nt = 0; nt < 8; nt++) {
            t0 = fmaxf(t0, fmaxf(sacc[nt][0], sacc[nt][1]));
            t1 = fmaxf(t1, fmaxf(sacc[nt][2], sacc[nt][3]));
        }
        t0 = fmaxf(t0, __shfl_xor_sync(0xffffffffu, t0, 1));
        t0 = fmaxf(t0, __shfl_xor_sync(0xffffffffu, t0, 2));
        t1 = fmaxf(t1, __shfl_xor_sync(0xffffffffu, t1, 1));
        t1 = fmaxf(t1, __shfl_xor_sync(0xffffffffu, t1, 2));
        float nm0 = fmaxf(m0, sc*t0), nm1 = fmaxf(m1, sc*t1);
        float f0 = __expf(m0 - nm0), f1 = __expf(m1 - nm1);
        float s0 = 0.f, s1 = 0.f;
#pragma unroll
        for (int nt = 0; nt < 8; nt++) {
            sacc[nt][0] = __expf(fmaf(sc, sacc[nt][0], -nm0));
            sacc[nt][1] = __expf(fmaf(sc, sacc[nt][1], -nm0));
            sacc[nt][2] = __expf(fmaf(sc, sacc[nt][2], -nm1));
            sacc[nt][3] = __expf(fmaf(sc, sacc[nt][3], -nm1));
            s0 += sacc[nt][0] + sacc[nt][1];
            s1 += sacc[nt][2] + sacc[nt][3];
        }
        s0 += __shfl_xor_sync(0xffffffffu, s0, 1);
        s0 += __shfl_xor_sync(0xffffffffu, s0, 2);
        s1 += __shfl_xor_sync(0xffffffffu, s1, 1);
        s1 += __shfl_xor_sync(0xffffffffu, s1, 2);
        l0 = l0*f0 + s0; l1 = l1*f1 + s1;
        m0 = nm0; m1 = nm1;
#pragma unroll
        for (int nt = 0; nt < 8; nt++) {
            o[nt][0] *= f0; o[nt][1] *= f0; o[nt][2] *= f1; o[nt][3] *= f1;
        }
#pragma unroll
        for (int ks = 0; ks < 8; ks++) {
            float v0 = __shfl_sync(0xffffffffu, sacc[ks][0], srcA);
            float v1 = __shfl_sync(0xffffffffu, sacc[ks][1], srcA);
            float v2 = __shfl_sync(0xffffffffu, sacc[ks][2], srcA);
            float v3 = __shfl_sync(0xffffffffu, sacc[ks][3], srcA);
            float w0 = __shfl_sync(0xffffffffu, sacc[ks][0], srcB);
            float w1 = __shfl_sync(0xffffffffu, sacc[ks][1], srcB);
            float w2 = __shfl_sync(0xffffffffu, sacc[ks][2], srcB);
            float w3 = __shfl_sync(0xffffffffu, sacc[ks][3], srcB);
            uint32_t af[4];
            af[0] = tf32rn(odd ? v1 : v0);
            af[1] = tf32rn(odd ? v3 : v2);
            af[2] = tf32rn(odd ? w1 : w0);
            af[3] = tf32rn(odd ? w3 : w2);
#pragma unroll
            for (int nt = 0; nt < 8; nt++) {
                uint32_t bf[2];
                const uint32_t* bp = Vs + (nt*8 + gid)*68 + ks*8 + tig;
                bf[0] = bp[0]; bf[1] = bp[4];
                mma1688(o[nt], af, bf);
            }
        }
        __syncthreads();
        if (kt + 2 < 24) copy_tile(kt + 2, kt & 1);
    }

    const long rowg = ((long)(half*48 + z))*1024 + qt*128 + wid*16 + gid;
    float* po0 = PO + rowg*64;
    float* po1 = PO + (rowg + 8)*64;
#pragma unroll
    for (int nt = 0; nt < 8; nt++) {
        *(float2*)(po0 + nt*8 + 2*tig) = make_float2(o[nt][0], o[nt][1]);
        *(float2*)(po1 + nt*8 + 2*tig) = make_float2(o[nt][2], o[nt][3]);
    }
    if (tig == 0) {
        ML[rowg*2]       = m0; ML[rowg*2 + 1]       = l0;
        ML[(rowg+8)*2]   = m1; ML[(rowg+8)*2 + 1]   = l1;
    }
}

// merge two kv-halves; output rounded to tf32 (consumed by output-proj GEMM)
__global__ __launch_bounds__(256)
void flash_merge(const float* __restrict__ PO, const float* __restrict__ ML,
                 float* __restrict__ CTXB3)
{
    const int z = blockIdx.y;
    const int s = z >> 4, b = (z >> 3) & 1, h = z & 7;
    const int row = blockIdx.x*128 + (threadIdx.x >> 1);
    const int cof = (threadIdx.x & 1) * 32;

    const long rA = (long)z*1024 + row;
    const long rB = (long)(48 + z)*1024 + row;
    float ma = ML[rA*2], la = ML[rA*2+1];
    float mb = ML[rB*2], lb = ML[rB*2+1];
    float m  = fmaxf(ma, mb);
    float fa = __expf(ma - m), fb = __expf(mb - m);
    float inv = 1.0f / (la*fa + lb*fb);
    fa *= inv; fb *= inv;

    const float* pa = PO + rA*64 + cof;
    const float* pb = PO + rB*64 + cof;
    float* dst = CTXB3 + (long)s*1048576 + ((long)(b*1024 + row))*512 + h*64 + cof;
#pragma unroll
    for (int i = 0; i < 8; i++) {
        float4 va = *(const float4*)(pa + i*4);
        float4 vb = *(const float4*)(pb + i*4);
        float4 r;
        r.x = tf32rnf(va.x*fa + vb.x*fb); r.y = tf32rnf(va.y*fa + vb.y*fb);
        r.z = tf32rnf(va.z*fa + vb.z*fb); r.w = tf32rnf(va.w*fa + vb.w*fb);
        *(float4*)(dst + i*4) = r;
    }
}

// ---------------------------------------------------------------------------
// scale_gram
// ---------------------------------------------------------------------------
__global__ __launch_bounds__(256)
void scale_gram(const float* __restrict__ QBt3, const float* __restrict__ KMt,
                const float* __restrict__ GQ, const float* __restrict__ GK,
                float* __restrict__ SCALE)
{
    const int z = blockIdx.x;
    const int s = z >> 4, bh = z & 15;
    const float* Qt = QBt3 + (long)s*1048576 + (long)bh*65536;
    const float* Kt = KMt + (long)bh*196608;
    __shared__ float sq[64], sk[64], red[256];
    const int tid = threadIdx.x;
    {
        int i = tid >> 2, part = tid & 3;
        float su = 0.f;
        for (int m = part; m < 1024; m += 4) su += Qt[(long)i*1024 + m];
        su += __shfl_xor_sync(0xffffffffu, su, 1);
        su += __shfl_xor_sync(0xffffffffu, su, 2);
        if (part == 0) sq[i] = su;
        float t = 0.f;
        for (int m = part; m < 3072; m += 4) t += Kt[(long)i*3072 + m];
        t += __shfl_xor_sync(0xffffffffu, t, 1);
        t += __shfl_xor_sync(0xffffffffu, t, 2);
        if (part == 0) sk[i] = t;
    }
    __syncthreads();
    float a = (tid < 64) ? sq[tid]*sk[tid] : 0.f;
    red[tid] = a;
    __syncthreads();
    for (int o = 128; o > 0; o >>= 1) {
        if (tid < o) red[tid] += red[tid+o];
        __syncthreads();
    }
    float sx = red[0];
    __syncthreads();
    const float* gq = GQ + (long)z*8192;
    const float* gk = GK + (long)bh*8192;
    float a2 = 0.f;
    for (int i = tid; i < 4096; i += 256) a2 = fmaf(gq[i], gk[i], a2);
    red[tid] = a2;
    __syncthreads();
    for (int o = 128; o > 0; o >>= 1) {
        if (tid < o) red[tid] += red[tid+o];
        __syncthreads();
    }
    if (tid == 0) {
        const float cnt = 1024.0f * 3072.0f;
        float mu  = sx / cnt;
        float var = red[0] / cnt - mu*mu;
        SCALE[z]  = rsqrtf(fmaxf(var, 0.f) + 1e-5f);
    }
}

// ---------------------------------------------------------------------------
// stats_final / softmax_rows (rounds output) / kvs_transpose
// ---------------------------------------------------------------------------
__global__ __launch_bounds__(256)
void stats_final(const float* __restrict__ part, int nblk, long perZ,
                 float* __restrict__ scale)
{
    int z = blockIdx.x;
    float s = 0.f, ss = 0.f;
    for (int i = threadIdx.x; i < nblk; i += 256) {
        s  += part[((long)z*nblk + i)*2];
        ss += part[((long)z*nblk + i)*2 + 1];
    }
    __shared__ float a[256], b2[256];
    a[threadIdx.x] = s; b2[threadIdx.x] = ss;
    __syncthreads();
    for (int o = 128; o > 0; o >>= 1) {
        if (threadIdx.x < o) { a[threadIdx.x] += a[threadIdx.x+o]; b2[threadIdx.x] += b2[threadIdx.x+o]; }
        __syncthreads();
    }
    if (threadIdx.x == 0) {
        float mu  = a[0] / (float)perZ;
        float var = b2[0] / (float)perZ - mu*mu;
        scale[z]  = rsqrtf(fmaxf(var, 0.f) + 1e-5f);
    }
}

template<int PER>
__global__ __launch_bounds__(256)
void softmax_rows(float* __restrict__ x, int L,
                  const float* __restrict__ scale, int rowsPerScale)
{
    long row = blockIdx.x;
    float s  = scale[row / rowsPerScale];
    float* p = x + row * (long)L;

    float v[PER];
    float mx = -1e30f;
#pragma unroll
    for (int i = 0; i < PER; i++) {
        v[i] = p[threadIdx.x + i*256] * s;
        mx = fmaxf(mx, v[i]);
    }
    __shared__ float sh[8];
    for (int o = 16; o > 0; o >>= 1) mx = fmaxf(mx, __shfl_xor_sync(0xffffffffu, mx, o));
    if ((threadIdx.x & 31) == 0) sh[threadIdx.x >> 5] = mx;
    __syncthreads();
    mx = sh[0];
#pragma unroll
    for (int i = 1; i < 8; i++) mx = fmaxf(mx, sh[i]);

    float sum = 0.f;
#pragma unroll
    for (int i = 0; i < PER; i++) { v[i] = __expf(v[i] - mx); sum += v[i]; }
    __shared__ float sh2[8];
    for (int o = 16; o > 0; o >>= 1) sum += __shfl_xor_sync(0xffffffffu, sum, o);
    if ((threadIdx.x & 31) == 0) sh2[threadIdx.x >> 5] = sum;
    __syncthreads();
    sum = 0.f;
#pragma unroll
    for (int i = 0; i < 8; i++) sum += sh2[i];

    float inv = 1.0f / sum;
#pragma unroll
    for (int i = 0; i < PER; i++) p[threadIdx.x + i*256] = tf32rnf(v[i] * inv);
}

__global__ void kvs_transpose(const float* __restrict__ ctxc, float* __restrict__ kvs)
{
    int z = blockIdx.z;
    int b = z / 3, j = z % 3;
    const float* src = ctxc + (long)b*1536*1024 + (long)j*512*1024;
    float*       dst = kvs  + (long)b*3072*512  + (long)j*1024*512;

    __shared__ float t[32][33];
    int n0 = blockIdx.x*32, e0 = blockIdx.y*32;
    int tx = threadIdx.x, ty = threadIdx.y;
#pragma unroll
    for (int i = 0; i < 32; i += 8)
        t[ty+i][tx] = src[(long)(e0+ty+i)*1024 + (n0+tx)];
    __syncthreads();
#pragma unroll
    for (int i = 0; i < 32; i += 8)
        dst[(long)(n0+ty+i)*512 + (e0+tx)] = t[tx][ty+i];
}

// ---------------------------------------------------------------------------
// Host orchestration (graph-capturable: kernel launches only)
// ---------------------------------------------------------------------------
static constexpr int GEMM_SMEM128 = 2 * (128*36 + 128*36) * 4;   // 73728
static constexpr int GEMM_SMEM64  = 2 * (128*36 +  64*36) * 4;   // 55296
static constexpr int FLASH_SMEM   = 4 * 64 * 68 * 4;             // 69632

extern "C" void kernel_launch(void* const* d_in, const int* in_sizes, int n_in,
                              void* d_out, int out_size)
{
    const float* emb[3] = {(const float*)d_in[0], (const float*)d_in[1], (const float*)d_in[2]};
    const float* embC   = (const float*)d_in[3];
    const float* Wq[3]  = {(const float*)d_in[4], (const float*)d_in[5], (const float*)d_in[6]};
    const float* Wk     = (const float*)d_in[7];
    const float* Wv     = (const float*)d_in[8];
    const float* WqC    = (const float*)d_in[9];
    const float* WkC    = (const float*)d_in[10];
    const float* WvC    = (const float*)d_in[11];
    const float* Wo[3]  = {(const float*)d_in[12], (const float*)d_in[13], (const float*)d_in[14]};
    float* out = (float*)d_out;

    float *QCt,*KCt,*VC,*ATTC,*CTXC,*KVS,*KM,*VMt,*QB3,*QBt3,*KMt,*GQ,*GK,*PO,*ML,*CTXB3,*PART,*SCALE;
    float *embCr,*embr,*WqCr,*WkCr,*WvCr,*Wkr,*Wvr,*Wqr,*Wor;
    cudaGetSymbolAddress((void**)&QCt,  g_QCt);
    cudaGetSymbolAddress((void**)&KCt,  g_KCt);
    cudaGetSymbolAddress((void**)&VC,   g_VC);
    cudaGetSymbolAddress((void**)&ATTC, g_ATTC);
    cudaGetSymbolAddress((void**)&CTXC, g_CTXC);
    cudaGetSymbolAddress((void**)&KVS,  g_KVS);
    cudaGetSymbolAddress((void**)&KM,   g_KM);
    cudaGetSymbolAddress((void**)&VMt,  g_VMt);
    cudaGetSymbolAddress((void**)&QB3,  g_QB3);
    cudaGetSymbolAddress((void**)&QBt3, g_QBt3);
    cudaGetSymbolAddress((void**)&KMt,  g_KMt);
    cudaGetSymbolAddress((void**)&GQ,   g_GQ);
    cudaGetSymbolAddress((void**)&GK,   g_GK);
    cudaGetSymbolAddress((void**)&PO,   g_PO);
    cudaGetSymbolAddress((void**)&ML,   g_ML);
    cudaGetSymbolAddress((void**)&CTXB3,g_CTXB3);
    cudaGetSymbolAddress((void**)&PART, g_PART);
    cudaGetSymbolAddress((void**)&SCALE,g_SCALE);
    cudaGetSymbolAddress((void**)&embCr,g_embCr);
    cudaGetSymbolAddress((void**)&embr, g_embr);
    cudaGetSymbolAddress((void**)&WqCr, g_WqCr);
    cudaGetSymbolAddress((void**)&WkCr, g_WkCr);
    cudaGetSymbolAddress((void**)&WvCr, g_WvCr);
    cudaGetSymbolAddress((void**)&Wkr,  g_Wkr);
    cudaGetSymbolAddress((void**)&Wvr,  g_Wvr);
    cudaGetSymbolAddress((void**)&Wqr,  g_Wqr);
    cudaGetSymbolAddress((void**)&Wor,  g_Wor);

    cudaFuncSetAttribute((const void*)mma_gemm<128,false,false>, cudaFuncAttributeMaxDynamicSharedMemorySize, GEMM_SMEM128);
    cudaFuncSetAttribute((const void*)mma_gemm<128,true ,false>, cudaFuncAttributeMaxDynamicSharedMemorySize, GEMM_SMEM128);
    cudaFuncSetAttribute((const void*)mma_gemm<128,false,true >, cudaFuncAttributeMaxDynamicSharedMemorySize, GEMM_SMEM128);
    cudaFuncSetAttribute((const void*)mma_gemm<64 ,false,false>, cudaFuncAttributeMaxDynamicSharedMemorySize, GEMM_SMEM64);
    cudaFuncSetAttribute((const void*)flash_attn2, cudaFuncAttributeMaxDynamicSharedMemorySize, FLASH_SMEM);

    // ---- 0) pre-round all external inputs to tf32 ----
    {
        RoundJobs j;
        j.src[0]  = (const float4*)embC;   j.dst[0]  = (float4*)embCr;            j.n4[0]  = 2*1024*1536/4;
        j.src[1]  = (const float4*)emb[0]; j.dst[1]  = (float4*)embr;             j.n4[1]  = 1048576/4;
        j.src[2]  = (const float4*)emb[1]; j.dst[2]  = (float4*)(embr+1048576);   j.n4[2]  = 1048576/4;
        j.src[3]  = (const float4*)emb[2]; j.dst[3]  = (float4*)(embr+2097152);   j.n4[3]  = 1048576/4;
        j.src[4]  = (const float4*)WqC;    j.dst[4]  = (float4*)WqCr;             j.n4[4]  = 1536*1536/4;
        j.src[5]  = (const float4*)WkC;    j.dst[5]  = (float4*)WkCr;             j.n4[5]  = 1536*1536/4;
        j.src[6]  = (const float4*)WvC;    j.dst[6]  = (float4*)WvCr;             j.n4[6]  = 1536*1536/4;
        j.src[7]  = (const float4*)Wk;     j.dst[7]  = (float4*)Wkr;              j.n4[7]  = 512*512/4;
        j.src[8]  = (const float4*)Wv;     j.dst[8]  = (float4*)Wvr;              j.n4[8]  = 512*512/4;
        j.src[9]  = (const float4*)Wq[0];  j.dst[9]  = (float4*)Wqr;              j.n4[9]  = 512*512/4;
        j.src[10] = (const float4*)Wq[1];  j.dst[10] = (float4*)(Wqr+262144);     j.n4[10] = 512*512/4;
        j.src[11] = (const float4*)Wq[2];  j.dst[11] = (float4*)(Wqr+524288);     j.n4[11] = 512*512/4;
        j.src[12] = (const float4*)Wo[0];  j.dst[12] = (float4*)Wor;              j.n4[12] = 512*512/4;
        j.src[13] = (const float4*)Wo[1];  j.dst[13] = (float4*)(Wor+262144);     j.n4[13] = 512*512/4;
        j.src[14] = (const float4*)Wo[2];  j.dst[14] = (float4*)(Wor+524288);     j.n4[14] = 512*512/4;
        round_many<<<dim3(96,15),256>>>(j);
    }

    // ---- 1) channel projections (outputs rounded: feed further GEMMs) ----
    mma_gemm<128,false,true><<<dim3(8,12,2),256,GEMM_SMEM128>>>(WqCr, embCr, QCt, 1536, 1536,1536,1024,
        0,0, 1572864,0, 1572864,0, 1, nullptr);
    mma_gemm<128,false,true><<<dim3(8,12,2),256,GEMM_SMEM128>>>(WkCr, embCr, KCt, 1536, 1536,1536,1024,
        0,0, 1572864,0, 1572864,0, 1, nullptr);
    mma_gemm<128,false,true><<<dim3(12,16,1),256,GEMM_SMEM128>>>(embCr, WvCr, VC, 1536, 1536,1536,1536,
        0,0, 0,0, 0,0, 1, nullptr);

    // ---- 2) channel attention (stats fused; raw output, softmax rounds) ----
    mma_gemm<128,true,false><<<dim3(12,12,2),256,GEMM_SMEM128>>>(QCt, KCt, ATTC, 1024, 1024,1024,1536,
        1572864,0, 1572864,0, 2359296,0, 1, PART);
    stats_final<<<2,256>>>(PART, 144, 2359296L, SCALE);
    softmax_rows<6><<<2*1536,256>>>(ATTC, 1536, SCALE, 1536);

    mma_gemm<128,false,true><<<dim3(8,12,2),256,GEMM_SMEM128>>>(ATTC, VC, CTXC, 1536, 1536,1536,1024,
        2359296,0, 1572864,0, 1572864,0, 1, nullptr);

    // ---- 3) KV_S build + K/V projections ----
    kvs_transpose<<<dim3(32,16,6),dim3(32,8)>>>(CTXC, KVS);
    mma_gemm<128,false,true><<<dim3(4,48,1),256,GEMM_SMEM128>>>(KVS, Wkr, KM, 512, 512,512,512,
        0,0, 0,0, 0,0, 1, nullptr);
    mma_gemm<128,false,true><<<dim3(24,4,2),256,GEMM_SMEM128>>>(Wvr, KVS, VMt, 512, 512,512,3072,
        0,0, 1572864,0, 1572864,0, 1, nullptr);
    mma_gemm<128,false,true><<<dim3(24,4,2),256,GEMM_SMEM128>>>(Wkr, KVS, KMt, 512, 512,512,3072,
        0,0, 1572864,0, 1572864,0, 1, nullptr);

    // ---- GK[z]=K_h^T K_h ----
    mma_gemm<64,false,false><<<dim3(1,1,16),256,GEMM_SMEM64>>>(KMt, KMt, GK, 3072, 3072,3072,64,
        1572864,196608, 1572864,196608, 65536,8192, 8, nullptr);

    // ---- 4) Q projections (both orientations) ----
    for (int s = 0; s < 3; s++) {
        mma_gemm<128,false,true><<<dim3(4,16,1),256,GEMM_SMEM128>>>(embr + (long)s*1048576,
            Wqr + (long)s*262144, QB3 + (long)s*1048576,
            512, 512,512,512, 0,0, 0,0, 0,0, 1, nullptr);
        mma_gemm<128,false,true><<<dim3(8,4,2),256,GEMM_SMEM128>>>(Wqr + (long)s*262144,
            embr + (long)s*1048576, QBt3 + (long)s*1048576,
            512, 512,512,1024, 0,0, 524288,0, 524288,0, 1, nullptr);
    }
    mma_gemm<64,false,false><<<dim3(1,1,48),256,GEMM_SMEM64>>>(QBt3, QBt3, GQ, 1024, 1024,1024,64,
        1048576,65536, 1048576,65536, 131072,8192, 16, nullptr);
    scale_gram<<<48,256>>>(QBt3, KMt, GQ, GK, SCALE);

    // ---- 5) batched flash attention + merge ----
    flash_attn2<<<dim3(8,48,2),256,FLASH_SMEM>>>(QB3, KM, VMt, SCALE, PO, ML);
    flash_merge<<<dim3(8,48),256>>>(PO, ML, CTXB3);

    // ---- 6) output projections ----
    for (int s = 0; s < 3; s++)
        mma_gemm<128,false,false><<<dim3(4,16,1),256,GEMM_SMEM128>>>(CTXB3 + (long)s*1048576,
            Wor + (long)s*262144, out + (long)s*1048576,
            512, 512,512,512, 0,0, 0,0, 0,0, 1, nullptr);
}